// round 15
// baseline (speedup 1.0000x reference)
#include <cuda_runtime.h>
#include <cstdint>

#define BB   8192
#define TT   128
#define HID  64
#define NTH  256   // lane quad (4k..4k+3) owns hidden unit k

// Precomputed input-path tables (filled by precompute_tables kernel).
// gTA[a*192+r] includes b_ih + W_ih@b_proj, plus b_hh folded for R,Z rows.
__device__ float gTA[7 * 192];
__device__ float gTAS[20 * 192];
__device__ float gWbet[192];

// Packed fp32x2 FMA: d = a*b + d (FFMA2, only emitted via PTX fma.rn.f32x2)
__device__ __forceinline__ void ffma2(unsigned long long &d,
                                      unsigned long long a,
                                      unsigned long long b) {
    asm("fma.rn.f32x2 %0, %1, %2, %0;" : "+l"(d) : "l"(a), "l"(b));
}
__device__ __forceinline__ float lo32(unsigned long long v) {
    return __uint_as_float((unsigned)v);
}
__device__ __forceinline__ float hi32(unsigned long long v) {
    return __uint_as_float((unsigned)(v >> 32));
}
__device__ __forceinline__ float red2(unsigned long long v) {
    return lo32(v) + hi32(v);
}

// Hardware tanh (single MUFU op; 16-cyc latency, rt 8)
__device__ __forceinline__ float tanh_mufu(float x) {
    float y;
    asm("tanh.approx.f32 %0, %1;" : "=f"(y) : "f"(x));
    return y;
}
// sigmoid(x) = 0.5*tanh(x/2) + 0.5  -> one MUFU + one FMA
__device__ __forceinline__ float sigm_mufu(float x) {
    return fmaf(tanh_mufu(0.5f * x), 0.5f, 0.5f);
}

// One block of 192 threads; thread r computes gate row r of all tables.
__global__ void precompute_tables(const float* __restrict__ E_actor,   // [7,8]
                                  const float* __restrict__ E_action,  // [4,8]
                                  const float* __restrict__ E_street,  // [5,4]
                                  const float* __restrict__ W_proj,    // [32,21]
                                  const float* __restrict__ b_proj,    // [32]
                                  const float* __restrict__ W_ih,      // [192,32]
                                  const float* __restrict__ b_ih,      // [192]
                                  const float* __restrict__ b_hh)      // [192]
{
    const int r = threadIdx.x;   // 0..191
    const int g = r >> 6;        // gate 0=R,1=Z,2=N
    float M[21];
    #pragma unroll
    for (int c = 0; c < 21; c++) {
        float s = 0.f;
        for (int i = 0; i < 32; i++) s += W_ih[r * 32 + i] * W_proj[i * 21 + c];
        M[c] = s;
    }
    float b0 = b_ih[r];
    for (int i = 0; i < 32; i++) b0 += W_ih[r * 32 + i] * b_proj[i];
    if (g < 2) b0 += b_hh[r];    // fold recurrent bias for R,Z gates

    for (int a = 0; a < 7; a++) {
        float s = b0;
        #pragma unroll
        for (int c = 0; c < 8; c++) s += M[c] * E_actor[a * 8 + c];
        gTA[a * 192 + r] = s;
    }
    for (int ac = 0; ac < 4; ac++) {
        float sa = 0.f;
        #pragma unroll
        for (int c = 0; c < 8; c++) sa += M[8 + c] * E_action[ac * 8 + c];
        for (int st = 0; st < 5; st++) {
            float s = sa;
            #pragma unroll
            for (int c = 0; c < 4; c++) s += M[16 + c] * E_street[st * 4 + c];
            gTAS[(ac * 5 + st) * 192 + r] = s;
        }
    }
    gWbet[r] = M[20];
}

__global__ __launch_bounds__(NTH, 3)
void gru_seq_kernel(const int*  __restrict__ actor,
                    const int*  __restrict__ action,
                    const int*  __restrict__ street,
                    const float* __restrict__ bet,
                    const int*  __restrict__ mask,            // bool->int32 [B,T]
                    const float* __restrict__ W_hh,           // [192,64]
                    const float* __restrict__ b_hh,           // [192]
                    float* __restrict__ out)                  // [B,64]
{
    __shared__ __align__(16) float TA_s[7 * 192];
    __shared__ __align__(16) float TAS_s[20 * 192];
    __shared__ __align__(16) float wbet_s[192];
    __shared__ __align__(16) float h_s[2][HID];   // double-buffered hidden
    __shared__ __align__(16) int4  u_s[TT];       // {aoff, coff, bet_bits, 0}

    const int j = threadIdx.x;
    const int b = blockIdx.x;           // sequence id
    const int q = j & 3;                // quarter within the unit's lane quad
    const int k = j >> 2;               // hidden unit 0..63
    const int p = q & 1;                // parity: 0 -> R row, 1 -> Z row
    const int rR = k, rZ = k + 64, rN = k + 128;
    const int rMine = p ? rZ : rR;

    // ---- load tables to shared (vectorized) ----
    {
        const float4* src1 = (const float4*)gTA;
        float4*       dst1 = (float4*)TA_s;
        for (int i = j; i < 7 * 192 / 4; i += NTH) dst1[i] = src1[i];
        const float4* src2 = (const float4*)gTAS;
        float4*       dst2 = (float4*)TAS_s;
        for (int i = j; i < 20 * 192 / 4; i += NTH) dst2[i] = src2[i];
        const float4* src3 = (const float4*)gWbet;
        float4*       dst3 = (float4*)wbet_s;
        for (int i = j; i < 192 / 4; i += NTH) dst3[i] = src3[i];
    }
    if (j < HID) { h_s[0][j] = 0.f; h_s[1][j] = 0.f; }

    // ---- per-thread W_hh quarter-rows (16 floats = 4 ulonglong2 each) ----
    ulonglong2 wR[4], wZ[4], wN[4];
    {
        const ulonglong2* pRp = (const ulonglong2*)(W_hh + rR * 64 + q * 16);
        const ulonglong2* pZp = (const ulonglong2*)(W_hh + rZ * 64 + q * 16);
        const ulonglong2* pNp = (const ulonglong2*)(W_hh + rN * 64 + q * 16);
        #pragma unroll
        for (int i = 0; i < 4; i++) { wR[i] = pRp[i]; wZ[i] = pZp[i]; wN[i] = pNp[i]; }
    }
    const float bhN = b_hh[rN];         // only N's recurrent bias stays separate

    // ---- sequence length from prefix-valid mask (int32 words) ----
    // (__syncthreads_count also orders the table fills above)
    const int len = __syncthreads_count((j < TT) && (mask[b * TT + j] != 0));

    const float wbMine = wbet_s[rMine];
    const float wbN    = wbet_s[rN];

    // ---- stage per-step uniforms: one int4 per t ----
    if (j < TT)
        u_s[j] = make_int4(actor[b * TT + j] * 192,
                           (action[b * TT + j] * 5 + street[b * TT + j]) * 192,
                           __float_as_int(bet[b * TT + j]), 0);
    __syncthreads();

    float hk = 0.f;                     // own h[k], register-carried

    // ---- recurrent loop: ONE barrier per step (double-buffered h) ----
    for (int t = 0; t < len; t++) {
        const int rd = t & 1, wr = rd ^ 1;
        const ulonglong2* hp = (const ulonglong2*)h_s[rd] + q * 4;

        // quarter-dots for the three gate rows of unit k (single chain each)
        unsigned long long aR = 0, aZ = 0, aN = 0;
        #pragma unroll
        for (int i = 0; i < 4; i++) {
            const ulonglong2 hv = hp[i];
            ffma2(aR, wR[i].x, hv.x);
            ffma2(aR, wR[i].y, hv.y);
            ffma2(aZ, wZ[i].x, hv.x);
            ffma2(aZ, wZ[i].y, hv.y);
            ffma2(aN, wN[i].x, hv.x);
            ffma2(aN, wN[i].y, hv.y);
        }
        const float pRq = red2(aR);     // quarter-sums
        const float pZq = red2(aZ);
        const float pNq = red2(aN);

        // xor-1: merge own-gate cross terms within each lane pair
        const float fwd  = p ? pRq : pZq;
        const float got  = __shfl_xor_sync(0xffffffffu, fwd, 1);
        const float pM2  = (p ? pZq : pRq) + got;   // own-gate sum of this pair
        const float pN2  = pNq + __shfl_xor_sync(0xffffffffu, pNq, 1);
        // xor-2: combine the two pair-sums -> full dots
        const float pMine = pM2 + __shfl_xor_sync(0xffffffffu, pM2, 2);
        const float pN    = pN2 + __shfl_xor_sync(0xffffffffu, pN2, 2);

        // per-step uniforms (single LDS.128, warp-uniform address)
        const int4  uv = u_s[t];
        const float bf = __int_as_float(uv.z);

        // split table loads by parity (duplicated across the two pairs)
        const float t1 = TA_s[uv.x + rMine];
        const float t2 = TAS_s[uv.y + rMine];
        const float t3 = p ? TAS_s[uv.y + rN] : TA_s[uv.x + rN];

        const float xgMine = t1 + t2 + wbMine * bf;
        const float xgN = t3 + __shfl_xor_sync(0xffffffffu, t3, 1) + wbN * bf;

        // own gate (even: r, odd: z), then swap across the pair
        const float gMine  = sigm_mufu(xgMine + pMine);
        const float gOther = __shfl_xor_sync(0xffffffffu, gMine, 1);
        const float r = p ? gOther : gMine;
        const float z = p ? gMine  : gOther;

        const float n = tanh_mufu(xgN + r * (pN + bhN));
        hk = n + z * (hk - n);
        if (q == 0) h_s[wr][k] = hk;

        __syncthreads();   // write buffer visible before next step reads
    }

    if (q == 0) out[(long long)b * HID + k] = hk;
}

extern "C" void kernel_launch(void* const* d_in, const int* in_sizes, int n_in,
                              void* d_out, int out_size) {
    const int*   actor    = (const int*)  d_in[0];
    const int*   action   = (const int*)  d_in[1];
    const int*   street   = (const int*)  d_in[2];
    const float* bet      = (const float*)d_in[3];
    const int*   mask     = (const int*)  d_in[4];
    const float* E_actor  = (const float*)d_in[5];
    const float* E_action = (const float*)d_in[6];
    const float* E_street = (const float*)d_in[7];
    const float* W_proj   = (const float*)d_in[8];
    const float* b_proj   = (const float*)d_in[9];
    const float* W_ih     = (const float*)d_in[10];
    const float* W_hh     = (const float*)d_in[11];
    const float* b_ih     = (const float*)d_in[12];
    const float* b_hh     = (const float*)d_in[13];
    float*       out      = (float*)      d_out;

    precompute_tables<<<1, 192>>>(E_actor, E_action, E_street,
                                  W_proj, b_proj, W_ih, b_ih, b_hh);
    gru_seq_kernel<<<BB, NTH>>>(actor, action, street, bet, mask,
                                W_hh, b_hh, out);
}

// round 17
// speedup vs baseline: 1.6389x; 1.6389x over previous
#include <cuda_runtime.h>
#include <cstdint>

#define BB   8192
#define TT   128
#define HID  64
#define NTH  128   // thread pair (2k,2k+1) owns hidden unit k

// Combined input table (filled by precompute_tables kernel):
// gT[(a*20 + c)*192 + r] = actor-a + combo-c contribution for gate row r,
// with b_ih + W_ih@b_proj folded in, and b_hh folded for R,Z rows.
// 140 * 192 * 4B = 107.5 KB -> L1-resident (smem usage is tiny).
__device__ float gT[140 * 192];
__device__ float gWbet[192];
__device__ float gbhN[64];

// Packed fp32x2 FMA: d = a*b + d (FFMA2, only emitted via PTX fma.rn.f32x2)
__device__ __forceinline__ void ffma2(unsigned long long &d,
                                      unsigned long long a,
                                      unsigned long long b) {
    asm("fma.rn.f32x2 %0, %1, %2, %0;" : "+l"(d) : "l"(a), "l"(b));
}
__device__ __forceinline__ float lo32(unsigned long long v) {
    return __uint_as_float((unsigned)v);
}
__device__ __forceinline__ float hi32(unsigned long long v) {
    return __uint_as_float((unsigned)(v >> 32));
}
__device__ __forceinline__ float red2(unsigned long long v) {
    return lo32(v) + hi32(v);
}

// Hardware tanh (single MUFU op; 16-cyc latency, rt 8)
__device__ __forceinline__ float tanh_mufu(float x) {
    float y;
    asm("tanh.approx.f32 %0, %1;" : "=f"(y) : "f"(x));
    return y;
}
// sigmoid(x) = 0.5*tanh(x/2) + 0.5  -> one MUFU + one FMA
__device__ __forceinline__ float sigm_mufu(float x) {
    return fmaf(tanh_mufu(0.5f * x), 0.5f, 0.5f);
}

// One block of 192 threads; thread r computes gate row r of all tables.
__global__ void precompute_tables(const float* __restrict__ E_actor,   // [7,8]
                                  const float* __restrict__ E_action,  // [4,8]
                                  const float* __restrict__ E_street,  // [5,4]
                                  const float* __restrict__ W_proj,    // [32,21]
                                  const float* __restrict__ b_proj,    // [32]
                                  const float* __restrict__ W_ih,      // [192,32]
                                  const float* __restrict__ b_ih,      // [192]
                                  const float* __restrict__ b_hh)      // [192]
{
    const int r = threadIdx.x;   // 0..191
    const int g = r >> 6;        // gate 0=R,1=Z,2=N
    float M[21];
    #pragma unroll
    for (int c = 0; c < 21; c++) {
        float s = 0.f;
        for (int i = 0; i < 32; i++) s += W_ih[r * 32 + i] * W_proj[i * 21 + c];
        M[c] = s;
    }
    float b0 = b_ih[r];
    for (int i = 0; i < 32; i++) b0 += W_ih[r * 32 + i] * b_proj[i];
    if (g < 2) b0 += b_hh[r];    // fold recurrent bias for R,Z gates

    float ta[7];
    for (int a = 0; a < 7; a++) {
        float s = b0;
        #pragma unroll
        for (int c = 0; c < 8; c++) s += M[c] * E_actor[a * 8 + c];
        ta[a] = s;
    }
    float tas[20];
    for (int ac = 0; ac < 4; ac++) {
        float sa = 0.f;
        #pragma unroll
        for (int c = 0; c < 8; c++) sa += M[8 + c] * E_action[ac * 8 + c];
        for (int st = 0; st < 5; st++) {
            float s = sa;
            #pragma unroll
            for (int c = 0; c < 4; c++) s += M[16 + c] * E_street[st * 4 + c];
            tas[ac * 5 + st] = s;
        }
    }
    for (int a = 0; a < 7; a++)
        for (int c = 0; c < 20; c++)
            gT[(a * 20 + c) * 192 + r] = ta[a] + tas[c];

    gWbet[r] = M[20];
    if (r < 64) gbhN[r] = b_hh[128 + r];
}

__global__ __launch_bounds__(NTH, 4)
void gru_seq_kernel(const int*  __restrict__ actor,
                    const int*  __restrict__ action,
                    const int*  __restrict__ street,
                    const float* __restrict__ bet,
                    const int*  __restrict__ mask,            // bool->int32 [B,T]
                    const float* __restrict__ W_hh,           // [192,64]
                    float* __restrict__ out)                  // [B,64]
{
    __shared__ __align__(16) float h_s[2][HID];   // double-buffered hidden
    __shared__ __align__(16) int2  u_s[TT];       // {table_off, bet_bits}

    const int j    = threadIdx.x;
    const int b    = blockIdx.x;        // sequence id
    const int k    = j >> 1;            // hidden unit 0..63
    const int half = j & 1;             // which 32-wide half of the dot
    const int rR = k, rZ = k + 64, rN = k + 128;
    const int rMine = half ? rZ : rR;   // even lane -> R row, odd -> Z row

    if (j < HID) { h_s[0][j] = 0.f; h_s[1][j] = 0.f; }

    // ---- per-thread W_hh half-rows (32 floats = 8 ulonglong2) in registers ----
    ulonglong2 wR[8], wZ[8], wN[8];
    {
        const ulonglong2* pR = (const ulonglong2*)(W_hh + rR * 64 + half * 32);
        const ulonglong2* pZ = (const ulonglong2*)(W_hh + rZ * 64 + half * 32);
        const ulonglong2* pN = (const ulonglong2*)(W_hh + rN * 64 + half * 32);
        #pragma unroll
        for (int i = 0; i < 8; i++) { wR[i] = pR[i]; wZ[i] = pZ[i]; wN[i] = pN[i]; }
    }
    const float bhN    = gbhN[k];
    const float wbMine = gWbet[rMine];
    const float wbN    = gWbet[rN];

    // ---- stage per-step uniforms: one int2 per t (combined table offset) ----
    u_s[j] = make_int2((actor[b * TT + j] * 20 +
                        action[b * TT + j] * 5 + street[b * TT + j]) * 192,
                       __float_as_int(bet[b * TT + j]));

    // ---- sequence length from prefix-valid mask (int32 words) ----
    // (__syncthreads_count also publishes u_s and h_s)
    const int len = __syncthreads_count(mask[b * TT + j] != 0);

    const float* __restrict__ Tb = gT;

    // prologue prefetch for t = 0
    int2  uv = u_s[0];
    float tM = __ldg(Tb + uv.x + rMine);
    float tN = __ldg(Tb + uv.x + rN);

    float hk = 0.f;                     // own h[k], register-carried

    // ---- recurrent loop: ONE barrier per step (double-buffered h) ----
    for (int t = 0; t < len; t++) {
        const int rd = t & 1, wr = rd ^ 1;
        const ulonglong2* hp = (const ulonglong2*)h_s[rd] + half * 8;

        // prefetch t+1 uniforms + table entries (immutable -> safe pre-barrier;
        // latency hides under this step's dot chain)
        const int  tn  = (t + 1 < TT) ? t + 1 : TT - 1;
        const int2 uvn = u_s[tn];
        const float tMn = __ldg(Tb + uvn.x + rMine);
        const float tNn = __ldg(Tb + uvn.x + rN);

        // half-dots for the three gate rows of unit k (single chain each)
        unsigned long long aR = 0, aZ = 0, aN = 0;
        #pragma unroll
        for (int i = 0; i < 8; i++) {
            const ulonglong2 hv = hp[i];
            ffma2(aR, wR[i].x, hv.x);
            ffma2(aR, wR[i].y, hv.y);
            ffma2(aZ, wZ[i].x, hv.x);
            ffma2(aZ, wZ[i].y, hv.y);
            ffma2(aN, wN[i].x, hv.x);
            ffma2(aN, wN[i].y, hv.y);
        }
        const float pRh = red2(aR);     // half-sums
        const float pZh = red2(aZ);
        const float pNh = red2(aN);

        // ONE shuffle merges pR for even and pZ for odd
        const float fwd   = half ? pRh : pZh;
        const float got   = __shfl_xor_sync(0xffffffffu, fwd, 1);
        const float pMine = (half ? pZh : pRh) + got;   // full dot of own gate
        // full pN in both lanes
        const float pN = pNh + __shfl_xor_sync(0xffffffffu, pNh, 1);

        const float bf = __int_as_float(uv.y);
        const float xgMine = tM + wbMine * bf;
        const float xgN    = tN + wbN * bf;

        // own gate (even: r, odd: z), then swap across the pair
        const float gMine  = sigm_mufu(xgMine + pMine);
        const float gOther = __shfl_xor_sync(0xffffffffu, gMine, 1);
        const float r = half ? gOther : gMine;
        const float z = half ? gMine  : gOther;

        const float n = tanh_mufu(xgN + r * (pN + bhN));
        hk = n + z * (hk - n);
        if (half == 0) h_s[wr][k] = hk;

        uv = uvn; tM = tMn; tN = tNn;   // rotate prefetch registers
        __syncthreads();   // write buffer visible before next step reads
    }

    if (half == 0) out[(long long)b * HID + k] = hk;
}

extern "C" void kernel_launch(void* const* d_in, const int* in_sizes, int n_in,
                              void* d_out, int out_size) {
    const int*   actor    = (const int*)  d_in[0];
    const int*   action   = (const int*)  d_in[1];
    const int*   street   = (const int*)  d_in[2];
    const float* bet      = (const float*)d_in[3];
    const int*   mask     = (const int*)  d_in[4];
    const float* E_actor  = (const float*)d_in[5];
    const float* E_action = (const float*)d_in[6];
    const float* E_street = (const float*)d_in[7];
    const float* W_proj   = (const float*)d_in[8];
    const float* b_proj   = (const float*)d_in[9];
    const float* W_ih     = (const float*)d_in[10];
    const float* W_hh     = (const float*)d_in[11];
    const float* b_ih     = (const float*)d_in[12];
    const float* b_hh     = (const float*)d_in[13];
    float*       out      = (float*)      d_out;

    precompute_tables<<<1, 192>>>(E_actor, E_action, E_street,
                                  W_proj, b_proj, W_ih, b_ih, b_hh);
    gru_seq_kernel<<<BB, NTH>>>(actor, action, street, bet, mask,
                                W_hh, out);
}